// round 16
// baseline (speedup 1.0000x reference)
#include <cuda_runtime.h>
#include <math.h>
#include <stdint.h>

// Static problem shape (HSTU_BSA: T=3200, H=8, D=128, B=4, N_MAX=1024)
#define TT 3200
#define HH 8
#define DD 128
#define BB 4
#define NN 1024
#define NB 32      // blocks per padded sequence
#define BSZ 32     // block size
#define SSEL 8     // top-k blocks
#define HD 1024    // H*D
#define SCALE 0.08838834764831845f   // D^-0.5
#define LN_EPS 1e-5f
#define KCP 132    // padded pitch for K tiles in shared (conflict-free lane-per-row float4)

// ---------------- scratch (device globals; no allocations allowed) ----------
__device__ __align__(16) float g_qp[BB*NN*HD];
__device__ __align__(16) float g_kp[BB*NN*HD];
__device__ __align__(16) float g_vp[BB*NN*HD];
__device__ __align__(16) float g_kcmp[BB*HH*NB*DD];
__device__ __align__(16) float g_vcmp[BB*HH*NB*DD];
__device__ float g_gcmp[BB*NN*HH];
__device__ float g_gslc[BB*NN*HH];
__device__ unsigned g_selmask[BB*HH*NN];
__device__ __align__(16) float g_ocmp[TT*HD];
__device__ __align__(16) float g_oslc[TT*HD];
__device__ int g_offs[BB+1];

__device__ __forceinline__ float silu_f(float x){ return x / (1.f + __expf(-x)); }
__device__ __forceinline__ float sigm_f(float x){ return 1.f / (1.f + __expf(-x)); }

// ---------------- K0: decode x_offsets (int32 or int64, sniffed) ------------
__global__ void k_offsets(const void* __restrict__ raw){
    if (threadIdx.x == 0 && blockIdx.x == 0){
        const int* i32 = (const int*)raw;
        bool ok32 = (i32[0] == 0) && (i32[BB] == TT);
        for (int i = 1; i <= BB; i++) if (i32[i] < i32[i-1]) ok32 = false;
        if (ok32){
            for (int i = 0; i <= BB; i++) g_offs[i] = i32[i];
        } else {
            const long long* i64 = (const long long*)raw;
            for (int i = 0; i <= BB; i++) g_offs[i] = (int)i64[i];
        }
    }
}

// ---------------- K1: jagged -> padded (and emit qp/kp outputs) -------------
__global__ void k_pad(const float* __restrict__ q, const float* __restrict__ k,
                      const float* __restrict__ v,
                      float* __restrict__ qp_out, float* __restrict__ kp_out,
                      int has_out)
{
    const float4* q4 = (const float4*)q;
    const float4* k4 = (const float4*)k;
    const float4* v4 = (const float4*)v;
    const int total = BB*NN*(HD/4);
    for (int i = blockIdx.x*blockDim.x + threadIdx.x; i < total; i += gridDim.x*blockDim.x){
        int c   = i & 255;         // float4 column within HD
        int row = i >> 8;          // b*NN + m
        int b   = row >> 10;
        int m   = row & (NN-1);
        int o0  = g_offs[b];
        int len = g_offs[b+1] - o0;
        float4 zq = make_float4(0.f,0.f,0.f,0.f), zk = zq, zv = zq;
        if (m < len){
            int t = o0 + m;
            zq = q4[t*256 + c];
            zk = k4[t*256 + c];
            zv = v4[t*256 + c];
        }
        ((float4*)g_qp)[i] = zq;
        ((float4*)g_kp)[i] = zk;
        ((float4*)g_vp)[i] = zv;
        if (has_out){
            ((float4*)qp_out)[i] = zq;
            ((float4*)kp_out)[i] = zk;
        }
    }
}

// ---------------- K2: block mean compression (k_cmp, v_cmp) -----------------
__global__ void k_compress(){
    int b  = blockIdx.x >> 5;
    int kb = blockIdx.x & 31;
    for (int idx = threadIdx.x; idx < HD; idx += blockDim.x){
        int base = (b*NN + kb*BSZ)*HD + idx;
        float sk = 0.f, sv = 0.f;
        #pragma unroll
        for (int j = 0; j < BSZ; j++){
            sk += g_kp[base + j*HD];
            sv += g_vp[base + j*HD];
        }
        int h = idx >> 7, d = idx & 127;
        int o = ((b*HH + h)*NB + kb)*DD + d;
        g_kcmp[o] = sk * (1.f/32.f);
        g_vcmp[o] = sv * (1.f/32.f);
    }
}

// ---------------- K3: per-head gates (sigmoid(q @ Wg + bg)) -----------------
__global__ void k_gates(const float* __restrict__ Wg, const float* __restrict__ bg){
    int row  = blockIdx.x;            // b*NN + m
    int h    = threadIdx.x >> 5;
    int lane = threadIdx.x & 31;
    const float* qr = g_qp + (size_t)row*HD + h*DD;
    const float* w  = Wg + h*DD*3;
    float s0 = 0.f, s1 = 0.f;
    #pragma unroll
    for (int d = lane; d < DD; d += 32){
        float qv = qr[d];
        s0 = fmaf(qv, w[d*3+0], s0);
        s1 = fmaf(qv, w[d*3+1], s1);
    }
    #pragma unroll
    for (int o = 16; o; o >>= 1){
        s0 += __shfl_xor_sync(0xffffffffu, s0, o);
        s1 += __shfl_xor_sync(0xffffffffu, s1, o);
    }
    if (lane == 0){
        g_gcmp[row*HH + h] = sigm_f(s0 + bg[h*3+0]);
        g_gslc[row*HH + h] = sigm_f(s1 + bg[h*3+1]);
    }
}

// ------- K4: compressed attention + top-k block selection + o_cmp -----------
// CTA per (qblk, h, b); 256 threads; warp w owns query rows r0=4w..4w+3.
__global__ void __launch_bounds__(256) k_cmp_attn(){
    extern __shared__ float sm[];
    float* KC = sm;                 // [32][KCP]
    float* VC = sm + 32*KCP;        // [32][128]
    float* Qs = VC + 32*128;        // [32][128]

    int qblk = blockIdx.x, h = blockIdx.y, b = blockIdx.z;
    int o0  = g_offs[b];
    int len = g_offs[b+1] - o0;
    if (qblk*BSZ >= len) return;
    int nc = qblk + 1;

    int tid = threadIdx.x, w = tid >> 5, lane = tid & 31;
    int r0 = w*4;

    for (int i = tid; i < 32*32; i += 256){
        int r = i >> 5, c = i & 31;
        ((float4*)Qs)[r*32 + c] =
            ((const float4*)g_qp)[(size_t)(b*NN + qblk*BSZ + r)*256 + h*32 + c];
    }
    for (int i = tid; i < nc*32; i += 256){
        int kb = i >> 5, c = i & 31;
        int go = ((b*HH + h)*NB + kb)*32 + c;
        ((float4*)(KC + kb*KCP))[c] = ((const float4*)g_kcmp)[go];
        ((float4*)VC)[kb*32 + c]    = ((const float4*)g_vcmp)[go];
    }
    __syncthreads();

    // ---- scores: lane = candidate block, 4 rows per warp ----
    const float4* kr = (const float4*)(KC + lane*KCP);
    const float4* qr[4];
    #pragma unroll
    for (int i = 0; i < 4; i++) qr[i] = (const float4*)(Qs + (r0+i)*128);

    float s[4] = {0.f,0.f,0.f,0.f};
    #pragma unroll 4
    for (int c = 0; c < 32; c++){
        float4 kc = kr[c];   // lanes >= nc read junk; fully masked below
        #pragma unroll
        for (int i = 0; i < 4; i++){
            float4 a = qr[i][c];
            s[i] = fmaf(a.x,kc.x, fmaf(a.y,kc.y, fmaf(a.z,kc.z, fmaf(a.w,kc.w, s[i]))));
        }
    }
    #pragma unroll
    for (int i = 0; i < 4; i++) s[i] *= SCALE;

    // ---- top-8 selection per row + silu weights ----
    unsigned causal = (nc >= 32) ? 0xffffffffu : ((1u << nc) - 1u);
    bool lc = (lane < nc);
    float p[4];
    #pragma unroll
    for (int i = 0; i < 4; i++){
        p[i] = lc ? silu_f(s[i]) : 0.f;
        unsigned sel;
        if (nc <= SSEL){
            sel = causal;
        } else {
            unsigned active = causal; sel = 0u;
            float myv = s[i];
            for (int it = 0; it < SSEL; it++){
                float vv = ((active >> lane) & 1u) ? myv : -3.4e38f;
                #pragma unroll
                for (int o = 16; o; o >>= 1) vv = fmaxf(vv, __shfl_xor_sync(0xffffffffu, vv, o));
                unsigned ball = __ballot_sync(0xffffffffu,
                                              (((active >> lane) & 1u) != 0u) && (myv == vv));
                int pick = __ffs((int)ball) - 1;
                sel |= (1u << pick);
                active &= ~(1u << pick);
            }
        }
        if (lane == 0) g_selmask[(b*HH + h)*NN + qblk*BSZ + r0 + i] = sel;
    }

    // ---- PV: lane = 4 dims, p broadcast via shuffle ----
    float4 acc[4];
    #pragma unroll
    for (int i = 0; i < 4; i++) acc[i] = make_float4(0.f,0.f,0.f,0.f);
    for (int kb = 0; kb < nc; kb++){
        float4 vv = ((const float4*)VC)[kb*32 + lane];
        #pragma unroll
        for (int i = 0; i < 4; i++){
            float pi = __shfl_sync(0xffffffffu, p[i], kb);
            acc[i].x = fmaf(pi, vv.x, acc[i].x);
            acc[i].y = fmaf(pi, vv.y, acc[i].y);
            acc[i].z = fmaf(pi, vv.z, acc[i].z);
            acc[i].w = fmaf(pi, vv.w, acc[i].w);
        }
    }
    #pragma unroll
    for (int i = 0; i < 4; i++){
        int m = qblk*BSZ + r0 + i;
        if (m < len){
            float g = g_gcmp[(b*NN + m)*HH + h];
            int t = o0 + m;
            float4 ov = acc[i];
            ov.x *= g; ov.y *= g; ov.z *= g; ov.w *= g;
            ((float4*)g_ocmp)[(t*HH + h)*32 + lane] = ov;
        }
    }
}

// ---------------- K5: selected (top-k gathered block) attention -------------
__global__ void __launch_bounds__(256) k_sel_attn(){
    extern __shared__ float sm[];
    float* Ks = sm;                 // [32][KCP]
    float* Vs = sm + 32*KCP;        // [32][128]
    float* Qs = Vs + 32*128;        // [32][128]
    unsigned* MS = (unsigned*)(Qs + 32*128);   // [32] row selection masks

    int qblk = blockIdx.x, h = blockIdx.y, b = blockIdx.z;
    int o0  = g_offs[b];
    int len = g_offs[b+1] - o0;
    if (qblk*BSZ >= len) return;

    int tid = threadIdx.x, w = tid >> 5, lane = tid & 31;
    int r0 = w*4;

    for (int i = tid; i < 32*32; i += 256){
        int r = i >> 5, c = i & 31;
        ((float4*)Qs)[r*32 + c] =
            ((const float4*)g_qp)[(size_t)(b*NN + qblk*BSZ + r)*256 + h*32 + c];
    }
    if (tid < 32){
        int m = qblk*BSZ + tid;
        MS[tid] = (m < len) ? g_selmask[(b*HH + h)*NN + m] : 0u;
    }
    __syncthreads();

    unsigned un = 0u;
    #pragma unroll
    for (int i = 0; i < 32; i++) un |= MS[i];
    unsigned rm[4];
    #pragma unroll
    for (int i = 0; i < 4; i++) rm[i] = MS[r0 + i];

    const float4* qr[4];
    #pragma unroll
    for (int i = 0; i < 4; i++) qr[i] = (const float4*)(Qs + (r0+i)*128);

    float4 acc[4];
    #pragma unroll
    for (int i = 0; i < 4; i++) acc[i] = make_float4(0.f,0.f,0.f,0.f);

    for (int kb = 0; kb <= qblk; kb++){
        if (!((un >> kb) & 1u)) continue;      // CTA-uniform skip
        __syncthreads();
        for (int i = tid; i < 32*32; i += 256){
            int j = i >> 5, c = i & 31;
            int gi = ((b*NN + kb*BSZ + j)*HH + h)*32 + c;
            ((float4*)(Ks + j*KCP))[c] = ((const float4*)g_kp)[gi];
            ((float4*)Vs)[j*32 + c]    = ((const float4*)g_vp)[gi];
        }
        __syncthreads();

        bool act[4];
        #pragma unroll
        for (int i = 0; i < 4; i++) act[i] = ((rm[i] >> kb) & 1u) != 0u;
        if (act[0] | act[1] | act[2] | act[3]){
            // scores: lane = key j within block
            const float4* kr = (const float4*)(Ks + lane*KCP);
            float s[4] = {0.f,0.f,0.f,0.f};
            #pragma unroll 4
            for (int c = 0; c < 32; c++){
                float4 kc = kr[c];
                #pragma unroll
                for (int i = 0; i < 4; i++){
                    if (act[i]){
                        float4 a = qr[i][c];
                        s[i] = fmaf(a.x,kc.x, fmaf(a.y,kc.y, fmaf(a.z,kc.z, fmaf(a.w,kc.w, s[i]))));
                    }
                }
            }
            bool diag = (kb == qblk);
            float p[4];
            #pragma unroll
            for (int i = 0; i < 4; i++){
                bool ok = act[i] && (!diag || lane <= (r0 + i));
                p[i] = ok ? silu_f(s[i]*SCALE) : 0.f;
            }
            // PV: lane = 4 dims
            #pragma unroll 4
            for (int j = 0; j < 32; j++){
                float4 vv = ((const float4*)Vs)[j*32 + lane];
                #pragma unroll
                for (int i = 0; i < 4; i++){
                    float pj = __shfl_sync(0xffffffffu, p[i], j);
                    if (act[i]){
                        acc[i].x = fmaf(pj, vv.x, acc[i].x);
                        acc[i].y = fmaf(pj, vv.y, acc[i].y);
                        acc[i].z = fmaf(pj, vv.z, acc[i].z);
                        acc[i].w = fmaf(pj, vv.w, acc[i].w);
                    }
                }
            }
        }
    }

    #pragma unroll
    for (int i = 0; i < 4; i++){
        int m = qblk*BSZ + r0 + i;
        if (m < len){
            float g = g_gslc[(b*NN + m)*HH + h];
            int t = o0 + m;
            float4 ov = acc[i];
            ov.x *= g; ov.y *= g; ov.z *= g; ov.w *= g;
            ((float4*)g_oslc)[(t*HH + h)*32 + lane] = ov;
        }
    }
}

// ---------------- K6: dual LayerNorm over H*D, gate by u, sum ---------------
__global__ void k_final(const float* __restrict__ u, float* __restrict__ out){
    __shared__ float red[64];
    int t = blockIdx.x;
    int tid = threadIdx.x;
    int w = tid >> 5, lane = tid & 31;

    float4 a = ((const float4*)g_ocmp)[t*256 + tid];
    float4 c = ((const float4*)g_oslc)[t*256 + tid];

    float sa = a.x + a.y + a.z + a.w;
    float sc = c.x + c.y + c.z + c.w;
    #pragma unroll
    for (int o = 16; o; o >>= 1){
        sa += __shfl_xor_sync(0xffffffffu, sa, o);
        sc += __shfl_xor_sync(0xffffffffu, sc, o);
    }
    if (lane == 0){ red[w] = sa; red[8 + w] = sc; }
    __syncthreads();
    if (tid == 0){
        float ta = 0.f, tc = 0.f;
        #pragma unroll
        for (int i = 0; i < 8; i++){ ta += red[i]; tc += red[8+i]; }
        red[16] = ta * (1.f/1024.f);
        red[17] = tc * (1.f/1024.f);
    }
    __syncthreads();
    float muA = red[16], muC = red[17];

    float dax = a.x-muA, day = a.y-muA, daz = a.z-muA, daw = a.w-muA;
    float dcx = c.x-muC, dcy = c.y-muC, dcz = c.z-muC, dcw = c.w-muC;
    float ssa = dax*dax + day*day + daz*daz + daw*daw;
    float ssc = dcx*dcx + dcy*dcy + dcz*dcz + dcw*dcw;
    #pragma unroll
    for (int o = 16; o; o >>= 1){
        ssa += __shfl_xor_sync(0xffffffffu, ssa, o);
        ssc += __shfl_xor_sync(0xffffffffu, ssc, o);
    }
    if (lane == 0){ red[w] = ssa; red[8 + w] = ssc; }
    __syncthreads();
    if (tid == 0){
        float ta = 0.f, tc = 0.f;
        #pragma unroll
        for (int i = 0; i < 8; i++){ ta += red[i]; tc += red[8+i]; }
        red[16] = ta * (1.f/1024.f);
        red[17] = tc * (1.f/1024.f);
    }
    __syncthreads();
    float rsA = rsqrtf(red[16] + LN_EPS);
    float rsC = rsqrtf(red[17] + LN_EPS);

    float4 uu = ((const float4*)u)[t*256 + tid];
    float4 o;
    o.x = (dax*rsA + dcx*rsC) * uu.x;
    o.y = (day*rsA + dcy*rsC) * uu.y;
    o.z = (daz*rsA + dcz*rsC) * uu.z;
    o.w = (daw*rsA + dcw*rsC) * uu.w;
    ((float4*)out)[t*256 + tid] = o;
}

// ---------------- launch -----------------------------------------------------
extern "C" void kernel_launch(void* const* d_in, const int* in_sizes, int n_in,
                              void* d_out, int out_size)
{
    const float* q  = (const float*)d_in[0];
    const float* k  = (const float*)d_in[1];
    const float* v  = (const float*)d_in[2];
    const float* u  = (const float*)d_in[3];
    const float* Wg = (const float*)d_in[4];
    const float* bg = (const float*)d_in[5];
    const void*  xo = d_in[6];

    float* out = (float*)d_out;
    int has_out = (out_size >= TT*HD + 2*BB*NN*HD) ? 1 : 0;
    float* qp_out = has_out ? (out + TT*HD) : nullptr;
    float* kp_out = has_out ? (out + TT*HD + BB*NN*HD) : nullptr;

    const int smem = (32*KCP + 32*128 + 32*128) * (int)sizeof(float) + 32*(int)sizeof(unsigned);
    cudaFuncSetAttribute(k_cmp_attn, cudaFuncAttributeMaxDynamicSharedMemorySize, smem);
    cudaFuncSetAttribute(k_sel_attn, cudaFuncAttributeMaxDynamicSharedMemorySize, smem);

    k_offsets<<<1, 32>>>(xo);
    k_pad<<<2048, 256>>>(q, k, v, qp_out, kp_out, has_out);
    k_compress<<<BB*NB, 256>>>();
    k_gates<<<BB*NN, 256>>>(Wg, bg);
    dim3 g45(NB, HH, BB);
    k_cmp_attn<<<g45, 256, smem>>>();
    k_sel_attn<<<g45, 256, smem>>>();
    k_final<<<TT, 256>>>(u, out);

    (void)in_sizes; (void)n_in;
}

// round 17
// speedup vs baseline: 1.0037x; 1.0037x over previous
#include <cuda_runtime.h>
#include <math.h>
#include <stdint.h>

// Static problem shape (HSTU_BSA: T=3200, H=8, D=128, B=4, N_MAX=1024)
#define TT 3200
#define HH 8
#define DD 128
#define BB 4
#define NN 1024
#define NB 32      // blocks per padded sequence
#define BSZ 32     // block size
#define SSEL 8     // top-k blocks
#define HD 1024    // H*D
#define SCALE 0.08838834764831845f   // D^-0.5
#define LN_EPS 1e-5f
#define KCP 132    // padded pitch for K tiles in shared (conflict-free lane-per-row float4)

// ---------------- scratch (device globals; no allocations allowed) ----------
__device__ __align__(16) float g_qp[BB*NN*HD];
__device__ __align__(16) float g_kp[BB*NN*HD];
__device__ __align__(16) float g_vp[BB*NN*HD];
__device__ __align__(16) float g_kcmp[BB*HH*NB*DD];
__device__ __align__(16) float g_vcmp[BB*HH*NB*DD];
__device__ float g_gcmp[BB*NN*HH];
__device__ float g_gslc[BB*NN*HH];
__device__ unsigned g_selmask[BB*HH*NN];
__device__ __align__(16) float g_ocmp[TT*HD];
__device__ __align__(16) float g_oslc[TT*HD];
__device__ int g_offs[BB+1];

__device__ __forceinline__ float silu_f(float x){ return x / (1.f + __expf(-x)); }
__device__ __forceinline__ float sigm_f(float x){ return 1.f / (1.f + __expf(-x)); }

// ---------------- K0: decode x_offsets (int32 or int64, sniffed) ------------
__global__ void k_offsets(const void* __restrict__ raw){
    if (threadIdx.x == 0 && blockIdx.x == 0){
        const int* i32 = (const int*)raw;
        bool ok32 = (i32[0] == 0) && (i32[BB] == TT);
        for (int i = 1; i <= BB; i++) if (i32[i] < i32[i-1]) ok32 = false;
        if (ok32){
            for (int i = 0; i <= BB; i++) g_offs[i] = i32[i];
        } else {
            const long long* i64 = (const long long*)raw;
            for (int i = 0; i <= BB; i++) g_offs[i] = (int)i64[i];
        }
    }
}

// ---------------- K1: jagged -> padded (and emit qp/kp outputs) -------------
__global__ void k_pad(const float* __restrict__ q, const float* __restrict__ k,
                      const float* __restrict__ v,
                      float* __restrict__ qp_out, float* __restrict__ kp_out,
                      int has_out)
{
    const float4* q4 = (const float4*)q;
    const float4* k4 = (const float4*)k;
    const float4* v4 = (const float4*)v;
    const int total = BB*NN*(HD/4);
    for (int i = blockIdx.x*blockDim.x + threadIdx.x; i < total; i += gridDim.x*blockDim.x){
        int c   = i & 255;         // float4 column within HD
        int row = i >> 8;          // b*NN + m
        int b   = row >> 10;
        int m   = row & (NN-1);
        int o0  = g_offs[b];
        int len = g_offs[b+1] - o0;
        float4 zq = make_float4(0.f,0.f,0.f,0.f), zk = zq, zv = zq;
        if (m < len){
            int t = o0 + m;
            zq = q4[t*256 + c];
            zk = k4[t*256 + c];
            zv = v4[t*256 + c];
        }
        ((float4*)g_qp)[i] = zq;
        ((float4*)g_kp)[i] = zk;
        ((float4*)g_vp)[i] = zv;
        if (has_out){
            ((float4*)qp_out)[i] = zq;
            ((float4*)kp_out)[i] = zk;
        }
    }
}

// ---------------- K2: block mean compression (k_cmp, v_cmp) -----------------
__global__ void k_compress(){
    int b  = blockIdx.x >> 5;
    int kb = blockIdx.x & 31;
    for (int idx = threadIdx.x; idx < HD; idx += blockDim.x){
        int base = (b*NN + kb*BSZ)*HD + idx;
        float sk = 0.f, sv = 0.f;
        #pragma unroll
        for (int j = 0; j < BSZ; j++){
            sk += g_kp[base + j*HD];
            sv += g_vp[base + j*HD];
        }
        int h = idx >> 7, d = idx & 127;
        int o = ((b*HH + h)*NB + kb)*DD + d;
        g_kcmp[o] = sk * (1.f/32.f);
        g_vcmp[o] = sv * (1.f/32.f);
    }
}

// ---------------- K3: per-head gates (sigmoid(q @ Wg + bg)) -----------------
__global__ void k_gates(const float* __restrict__ Wg, const float* __restrict__ bg){
    int row  = blockIdx.x;            // b*NN + m
    int h    = threadIdx.x >> 5;
    int lane = threadIdx.x & 31;
    const float* qr = g_qp + (size_t)row*HD + h*DD;
    const float* w  = Wg + h*DD*3;
    float s0 = 0.f, s1 = 0.f;
    #pragma unroll
    for (int d = lane; d < DD; d += 32){
        float qv = qr[d];
        s0 = fmaf(qv, w[d*3+0], s0);
        s1 = fmaf(qv, w[d*3+1], s1);
    }
    #pragma unroll
    for (int o = 16; o; o >>= 1){
        s0 += __shfl_xor_sync(0xffffffffu, s0, o);
        s1 += __shfl_xor_sync(0xffffffffu, s1, o);
    }
    if (lane == 0){
        g_gcmp[row*HH + h] = sigm_f(s0 + bg[h*3+0]);
        g_gslc[row*HH + h] = sigm_f(s1 + bg[h*3+1]);
    }
}

// ------- K4: compressed attention + top-k block selection + o_cmp -----------
// CTA per (qblk, h, b); 256 threads; warp w owns query rows r0=4w..4w+3.
__global__ void __launch_bounds__(256) k_cmp_attn(){
    extern __shared__ float sm[];
    float* KC = sm;                 // [32][KCP]
    float* VC = sm + 32*KCP;        // [32][128]
    float* Qs = VC + 32*128;        // [32][128]

    int qblk = blockIdx.x, h = blockIdx.y, b = blockIdx.z;
    int o0  = g_offs[b];
    int len = g_offs[b+1] - o0;
    if (qblk*BSZ >= len) return;
    int nc = qblk + 1;

    int tid = threadIdx.x, w = tid >> 5, lane = tid & 31;
    int r0 = w*4;

    for (int i = tid; i < 32*32; i += 256){
        int r = i >> 5, c = i & 31;
        ((float4*)Qs)[r*32 + c] =
            ((const float4*)g_qp)[(size_t)(b*NN + qblk*BSZ + r)*256 + h*32 + c];
    }
    for (int i = tid; i < nc*32; i += 256){
        int kb = i >> 5, c = i & 31;
        int go = ((b*HH + h)*NB + kb)*32 + c;
        ((float4*)(KC + kb*KCP))[c] = ((const float4*)g_kcmp)[go];
        ((float4*)VC)[kb*32 + c]    = ((const float4*)g_vcmp)[go];
    }
    __syncthreads();

    // ---- scores: lane = candidate block, 4 rows per warp ----
    const float4* kr = (const float4*)(KC + lane*KCP);
    const float4* qr[4];
    #pragma unroll
    for (int i = 0; i < 4; i++) qr[i] = (const float4*)(Qs + (r0+i)*128);

    float s[4] = {0.f,0.f,0.f,0.f};
    #pragma unroll 4
    for (int c = 0; c < 32; c++){
        float4 kc = kr[c];   // lanes >= nc read junk; fully masked below
        #pragma unroll
        for (int i = 0; i < 4; i++){
            float4 a = qr[i][c];
            s[i] = fmaf(a.x,kc.x, fmaf(a.y,kc.y, fmaf(a.z,kc.z, fmaf(a.w,kc.w, s[i]))));
        }
    }
    #pragma unroll
    for (int i = 0; i < 4; i++) s[i] *= SCALE;

    // ---- top-8 selection per row + silu weights ----
    unsigned causal = (nc >= 32) ? 0xffffffffu : ((1u << nc) - 1u);
    bool lc = (lane < nc);
    float p[4];
    #pragma unroll
    for (int i = 0; i < 4; i++){
        p[i] = lc ? silu_f(s[i]) : 0.f;
        unsigned sel;
        if (nc <= SSEL){
            sel = causal;
        } else {
            unsigned active = causal; sel = 0u;
            float myv = s[i];
            for (int it = 0; it < SSEL; it++){
                float vv = ((active >> lane) & 1u) ? myv : -3.4e38f;
                #pragma unroll
                for (int o = 16; o; o >>= 1) vv = fmaxf(vv, __shfl_xor_sync(0xffffffffu, vv, o));
                unsigned ball = __ballot_sync(0xffffffffu,
                                              (((active >> lane) & 1u) != 0u) && (myv == vv));
                int pick = __ffs((int)ball) - 1;
                sel |= (1u << pick);
                active &= ~(1u << pick);
            }
        }
        if (lane == 0) g_selmask[(b*HH + h)*NN + qblk*BSZ + r0 + i] = sel;
    }

    // ---- PV: lane = 4 dims, p broadcast via shuffle ----
    float4 acc[4];
    #pragma unroll
    for (int i = 0; i < 4; i++) acc[i] = make_float4(0.f,0.f,0.f,0.f);
    for (int kb = 0; kb < nc; kb++){
        float4 vv = ((const float4*)VC)[kb*32 + lane];
        #pragma unroll
        for (int i = 0; i < 4; i++){
            float pi = __shfl_sync(0xffffffffu, p[i], kb);
            acc[i].x = fmaf(pi, vv.x, acc[i].x);
            acc[i].y = fmaf(pi, vv.y, acc[i].y);
            acc[i].z = fmaf(pi, vv.z, acc[i].z);
            acc[i].w = fmaf(pi, vv.w, acc[i].w);
        }
    }
    #pragma unroll
    for (int i = 0; i < 4; i++){
        int m = qblk*BSZ + r0 + i;
        if (m < len){
            float g = g_gcmp[(b*NN + m)*HH + h];
            int t = o0 + m;
            float4 ov = acc[i];
            ov.x *= g; ov.y *= g; ov.z *= g; ov.w *= g;
            ((float4*)g_ocmp)[(t*HH + h)*32 + lane] = ov;
        }
    }
}

// ---------------- K5: selected (top-k gathered block) attention -------------
__global__ void __launch_bounds__(256) k_sel_attn(){
    extern __shared__ float sm[];
    float* Ks = sm;                 // [32][KCP]
    float* Vs = sm + 32*KCP;        // [32][128]
    float* Qs = Vs + 32*128;        // [32][128]
    unsigned* MS = (unsigned*)(Qs + 32*128);   // [32] row selection masks

    int qblk = blockIdx.x, h = blockIdx.y, b = blockIdx.z;
    int o0  = g_offs[b];
    int len = g_offs[b+1] - o0;
    if (qblk*BSZ >= len) return;

    int tid = threadIdx.x, w = tid >> 5, lane = tid & 31;
    int r0 = w*4;

    for (int i = tid; i < 32*32; i += 256){
        int r = i >> 5, c = i & 31;
        ((float4*)Qs)[r*32 + c] =
            ((const float4*)g_qp)[(size_t)(b*NN + qblk*BSZ + r)*256 + h*32 + c];
    }
    if (tid < 32){
        int m = qblk*BSZ + tid;
        MS[tid] = (m < len) ? g_selmask[(b*HH + h)*NN + m] : 0u;
    }
    __syncthreads();

    unsigned un = 0u;
    #pragma unroll
    for (int i = 0; i < 32; i++) un |= MS[i];
    unsigned rm[4];
    #pragma unroll
    for (int i = 0; i < 4; i++) rm[i] = MS[r0 + i];

    const float4* qr[4];
    #pragma unroll
    for (int i = 0; i < 4; i++) qr[i] = (const float4*)(Qs + (r0+i)*128);

    float4 acc[4];
    #pragma unroll
    for (int i = 0; i < 4; i++) acc[i] = make_float4(0.f,0.f,0.f,0.f);

    for (int kb = 0; kb <= qblk; kb++){
        if (!((un >> kb) & 1u)) continue;      // CTA-uniform skip
        __syncthreads();
        for (int i = tid; i < 32*32; i += 256){
            int j = i >> 5, c = i & 31;
            int gi = ((b*NN + kb*BSZ + j)*HH + h)*32 + c;
            ((float4*)(Ks + j*KCP))[c] = ((const float4*)g_kp)[gi];
            ((float4*)Vs)[j*32 + c]    = ((const float4*)g_vp)[gi];
        }
        __syncthreads();

        bool act[4];
        #pragma unroll
        for (int i = 0; i < 4; i++) act[i] = ((rm[i] >> kb) & 1u) != 0u;
        if (act[0] | act[1] | act[2] | act[3]){
            // scores: lane = key j within block
            const float4* kr = (const float4*)(Ks + lane*KCP);
            float s[4] = {0.f,0.f,0.f,0.f};
            #pragma unroll 4
            for (int c = 0; c < 32; c++){
                float4 kc = kr[c];
                #pragma unroll
                for (int i = 0; i < 4; i++){
                    if (act[i]){
                        float4 a = qr[i][c];
                        s[i] = fmaf(a.x,kc.x, fmaf(a.y,kc.y, fmaf(a.z,kc.z, fmaf(a.w,kc.w, s[i]))));
                    }
                }
            }
            bool diag = (kb == qblk);
            float p[4];
            #pragma unroll
            for (int i = 0; i < 4; i++){
                bool ok = act[i] && (!diag || lane <= (r0 + i));
                p[i] = ok ? silu_f(s[i]*SCALE) : 0.f;
            }
            // PV: lane = 4 dims
            #pragma unroll 4
            for (int j = 0; j < 32; j++){
                float4 vv = ((const float4*)Vs)[j*32 + lane];
                #pragma unroll
                for (int i = 0; i < 4; i++){
                    float pj = __shfl_sync(0xffffffffu, p[i], j);
                    if (act[i]){
                        acc[i].x = fmaf(pj, vv.x, acc[i].x);
                        acc[i].y = fmaf(pj, vv.y, acc[i].y);
                        acc[i].z = fmaf(pj, vv.z, acc[i].z);
                        acc[i].w = fmaf(pj, vv.w, acc[i].w);
                    }
                }
            }
        }
    }

    #pragma unroll
    for (int i = 0; i < 4; i++){
        int m = qblk*BSZ + r0 + i;
        if (m < len){
            float g = g_gslc[(b*NN + m)*HH + h];
            int t = o0 + m;
            float4 ov = acc[i];
            ov.x *= g; ov.y *= g; ov.z *= g; ov.w *= g;
            ((float4*)g_oslc)[(t*HH + h)*32 + lane] = ov;
        }
    }
}

// ---------------- K6: dual LayerNorm over H*D, gate by u, sum ---------------
__global__ void k_final(const float* __restrict__ u, float* __restrict__ out){
    __shared__ float red[64];
    int t = blockIdx.x;
    int tid = threadIdx.x;
    int w = tid >> 5, lane = tid & 31;

    float4 a = ((const float4*)g_ocmp)[t*256 + tid];
    float4 c = ((const float4*)g_oslc)[t*256 + tid];

    float sa = a.x + a.y + a.z + a.w;
    float sc = c.x + c.y + c.z + c.w;
    #pragma unroll
    for (int o = 16; o; o >>= 1){
        sa += __shfl_xor_sync(0xffffffffu, sa, o);
        sc += __shfl_xor_sync(0xffffffffu, sc, o);
    }
    if (lane == 0){ red[w] = sa; red[8 + w] = sc; }
    __syncthreads();
    if (tid == 0){
        float ta = 0.f, tc = 0.f;
        #pragma unroll
        for (int i = 0; i < 8; i++){ ta += red[i]; tc += red[8+i]; }
        red[16] = ta * (1.f/1024.f);
        red[17] = tc * (1.f/1024.f);
    }
    __syncthreads();
    float muA = red[16], muC = red[17];

    float dax = a.x-muA, day = a.y-muA, daz = a.z-muA, daw = a.w-muA;
    float dcx = c.x-muC, dcy = c.y-muC, dcz = c.z-muC, dcw = c.w-muC;
    float ssa = dax*dax + day*day + daz*daz + daw*daw;
    float ssc = dcx*dcx + dcy*dcy + dcz*dcz + dcw*dcw;
    #pragma unroll
    for (int o = 16; o; o >>= 1){
        ssa += __shfl_xor_sync(0xffffffffu, ssa, o);
        ssc += __shfl_xor_sync(0xffffffffu, ssc, o);
    }
    if (lane == 0){ red[w] = ssa; red[8 + w] = ssc; }
    __syncthreads();
    if (tid == 0){
        float ta = 0.f, tc = 0.f;
        #pragma unroll
        for (int i = 0; i < 8; i++){ ta += red[i]; tc += red[8+i]; }
        red[16] = ta * (1.f/1024.f);
        red[17] = tc * (1.f/1024.f);
    }
    __syncthreads();
    float rsA = rsqrtf(red[16] + LN_EPS);
    float rsC = rsqrtf(red[17] + LN_EPS);

    float4 uu = ((const float4*)u)[t*256 + tid];
    float4 o;
    o.x = (dax*rsA + dcx*rsC) * uu.x;
    o.y = (day*rsA + dcy*rsC) * uu.y;
    o.z = (daz*rsA + dcz*rsC) * uu.z;
    o.w = (daw*rsA + dcw*rsC) * uu.w;
    ((float4*)out)[t*256 + tid] = o;
}

// ---------------- launch -----------------------------------------------------
extern "C" void kernel_launch(void* const* d_in, const int* in_sizes, int n_in,
                              void* d_out, int out_size)
{
    const float* q  = (const float*)d_in[0];
    const float* k  = (const float*)d_in[1];
    const float* v  = (const float*)d_in[2];
    const float* u  = (const float*)d_in[3];
    const float* Wg = (const float*)d_in[4];
    const float* bg = (const float*)d_in[5];
    const void*  xo = d_in[6];

    float* out = (float*)d_out;
    int has_out = (out_size >= TT*HD + 2*BB*NN*HD) ? 1 : 0;
    float* qp_out = has_out ? (out + TT*HD) : nullptr;
    float* kp_out = has_out ? (out + TT*HD + BB*NN*HD) : nullptr;

    const int smem = (32*KCP + 32*128 + 32*128) * (int)sizeof(float) + 32*(int)sizeof(unsigned);
    cudaFuncSetAttribute(k_cmp_attn, cudaFuncAttributeMaxDynamicSharedMemorySize, smem);
    cudaFuncSetAttribute(k_sel_attn, cudaFuncAttributeMaxDynamicSharedMemorySize, smem);

    k_offsets<<<1, 32>>>(xo);
    k_pad<<<2048, 256>>>(q, k, v, qp_out, kp_out, has_out);
    k_compress<<<BB*NB, 256>>>();
    k_gates<<<BB*NN, 256>>>(Wg, bg);
    dim3 g45(NB, HH, BB);
    k_cmp_attn<<<g45, 256, smem>>>();
    k_sel_attn<<<g45, 256, smem>>>();
    k_final<<<TT, 256>>>(u, out);

    (void)in_sizes; (void)n_in;
}